// round 16
// baseline (speedup 1.0000x reference)
#include <cuda_runtime.h>
#include <math.h>

#define BB 128
#define TT 1024
#define DD 512
#define HH 512

// ---------------- scratch ----------------
__device__ float g_xp[(size_t)TT * BB * HH];   // [t][b][h]
__device__ float g_h[2][BB * HH];              // ping-pong hidden state
__device__ unsigned g_flag[16 * 16 * 32];      // flag[mg][ng] at 128B stride
__device__ unsigned g_ctr[16 * 32];
__device__ unsigned g_gen[16 * 32];

__device__ __forceinline__ unsigned long long ffma2(unsigned long long a,
                                                    unsigned long long b,
                                                    unsigned long long c) {
    unsigned long long d;
    asm("fma.rn.f32x2 %0, %1, %2, %3;" : "=l"(d) : "l"(a), "l"(b), "l"(c));
    return d;
}
__device__ __forceinline__ unsigned long long pack2(float x, float y) {
    unsigned long long d;
    asm("mov.b64 %0, {%1, %2};" : "=l"(d) : "f"(x), "f"(y));
    return d;
}
__device__ __forceinline__ void unpack2(unsigned long long v, float& x, float& y) {
    asm("mov.b64 {%0, %1}, %2;" : "=f"(x), "=f"(y) : "l"(v));
}

__device__ __forceinline__ unsigned atom_add_acqrel(unsigned* p, unsigned v) {
    unsigned old;
    asm volatile("atom.acq_rel.gpu.global.add.u32 %0, [%1], %2;"
                 : "=r"(old) : "l"(p), "r"(v) : "memory");
    return old;
}
__device__ __forceinline__ unsigned ld_acquire(unsigned* p) {
    unsigned v;
    asm volatile("ld.acquire.gpu.global.u32 %0, [%1];"
                 : "=r"(v) : "l"(p) : "memory");
    return v;
}
__device__ __forceinline__ void st_relaxed(unsigned* p, unsigned v) {
    asm volatile("st.relaxed.gpu.global.u32 [%0], %1;"
                 :: "l"(p), "r"(v) : "memory");
}
__device__ __forceinline__ void fence_rel_gpu() {
    asm volatile("fence.release.gpu;" ::: "memory");
}

__device__ __forceinline__ void group_barrier(int tid, unsigned* ctr, unsigned* gen) {
    __syncthreads();
    if (tid == 0) {
        unsigned g = ld_acquire(gen);
        unsigned tk = atom_add_acqrel(ctr, 1u);
        if (tk == 15u) {
            st_relaxed(ctr, 0u);
            atom_add_acqrel(gen, 1u);
        } else {
            while (ld_acquire(gen) == g) { }
        }
    }
    __syncthreads();
}

// =====================================================================
// Phase 1 v2: xp = x @ W_ih + b — double-buffered smem pipeline.
// One __syncthreads per k-tile; LDG for tile i+1 overlaps compute on i.
// =====================================================================
__global__ void __launch_bounds__(256) xp_gemm_kernel(
        const float* __restrict__ x, const float* __restrict__ Wih,
        const float* __restrict__ bias) {
    __shared__ float As[2][16][128];   // [buf][k][m]
    __shared__ float Bs[2][16][128];   // [buf][k][n]

    const int tid = threadIdx.x;
    const int tx = tid & 15;
    const int ty = tid >> 4;
    const int m0 = blockIdx.y * 128;
    const int n0 = blockIdx.x * 128;

    // load-slot mapping (q = 0,1):
    const int ia_row[2] = { (tid) >> 2, (tid + 256) >> 2 };
    const int ia_kc[2]  = { ((tid) & 3) * 4, ((tid + 256) & 3) * 4 };
    const int ib_kr[2]  = { (tid) >> 5, (tid + 256) >> 5 };
    const int ib_nc[2]  = { ((tid) & 31) * 4, ((tid + 256) & 31) * 4 };

    unsigned long long acc[8][4];
#pragma unroll
    for (int i = 0; i < 8; i++)
#pragma unroll
        for (int j = 0; j < 4; j++) acc[i][j] = 0ull;

    float4 av[2], bv[2];
    // prologue: load tile 0
#pragma unroll
    for (int q = 0; q < 2; q++) {
        av[q] = *(const float4*)&x[(size_t)(m0 + ia_row[q]) * DD + 0 + ia_kc[q]];
        bv[q] = *(const float4*)&Wih[(size_t)(0 + ib_kr[q]) * HH + n0 + ib_nc[q]];
    }
#pragma unroll
    for (int q = 0; q < 2; q++) {
        As[0][ia_kc[q] + 0][ia_row[q]] = av[q].x;
        As[0][ia_kc[q] + 1][ia_row[q]] = av[q].y;
        As[0][ia_kc[q] + 2][ia_row[q]] = av[q].z;
        As[0][ia_kc[q] + 3][ia_row[q]] = av[q].w;
        *(float4*)&Bs[0][ib_kr[q]][ib_nc[q]] = bv[q];
    }
    __syncthreads();

    int cur = 0;
    for (int k0 = 16; k0 <= DD; k0 += 16) {
        const bool more = (k0 < DD);
        if (more) {
#pragma unroll
            for (int q = 0; q < 2; q++) {
                av[q] = *(const float4*)&x[(size_t)(m0 + ia_row[q]) * DD + k0 + ia_kc[q]];
                bv[q] = *(const float4*)&Wih[(size_t)(k0 + ib_kr[q]) * HH + n0 + ib_nc[q]];
            }
        }

#pragma unroll
        for (int kk = 0; kk < 16; kk++) {
            float4 a0 = *(const float4*)&As[cur][kk][ty * 8];
            float4 a1 = *(const float4*)&As[cur][kk][ty * 8 + 4];
            const unsigned long long* bp =
                (const unsigned long long*)&Bs[cur][kk][tx * 8];
            unsigned long long b0 = bp[0], b1 = bp[1], b2 = bp[2], b3 = bp[3];
            float a[8] = {a0.x, a0.y, a0.z, a0.w, a1.x, a1.y, a1.z, a1.w};
#pragma unroll
            for (int i = 0; i < 8; i++) {
                unsigned long long ap = pack2(a[i], a[i]);
                acc[i][0] = ffma2(ap, b0, acc[i][0]);
                acc[i][1] = ffma2(ap, b1, acc[i][1]);
                acc[i][2] = ffma2(ap, b2, acc[i][2]);
                acc[i][3] = ffma2(ap, b3, acc[i][3]);
            }
        }

        if (more) {
            const int nb = cur ^ 1;
#pragma unroll
            for (int q = 0; q < 2; q++) {
                As[nb][ia_kc[q] + 0][ia_row[q]] = av[q].x;
                As[nb][ia_kc[q] + 1][ia_row[q]] = av[q].y;
                As[nb][ia_kc[q] + 2][ia_row[q]] = av[q].z;
                As[nb][ia_kc[q] + 3][ia_row[q]] = av[q].w;
                *(float4*)&Bs[nb][ib_kr[q]][ib_nc[q]] = bv[q];
            }
            __syncthreads();
            cur = nb;
        }
    }

    float4 bv0 = *(const float4*)&bias[n0 + tx * 8];
    float4 bv1 = *(const float4*)&bias[n0 + tx * 8 + 4];
    float bb8[8] = {bv0.x, bv0.y, bv0.z, bv0.w, bv1.x, bv1.y, bv1.z, bv1.w};
#pragma unroll
    for (int i = 0; i < 8; i++) {
        int mrow = m0 + ty * 8 + i;
        int b_ = mrow >> 10;
        int t_ = mrow & 1023;
        float f[8];
        unpack2(acc[i][0], f[0], f[1]);
        unpack2(acc[i][1], f[2], f[3]);
        unpack2(acc[i][2], f[4], f[5]);
        unpack2(acc[i][3], f[6], f[7]);
#pragma unroll
        for (int j = 0; j < 8; j++) f[j] += bb8[j];
        float* dst = &g_xp[((size_t)t_ * BB + b_) * HH + n0 + tx * 8];
        *(float4*)&dst[0] = make_float4(f[0], f[1], f[2], f[3]);
        *(float4*)&dst[4] = make_float4(f[4], f[5], f[6], f[7]);
    }
}

// =====================================================================
// Phase 2 v10 = v9 + phase stagger + earlier xp prefetch + fused polls.
// 256 CTAs x 256 thr (8 rows x 32 cols), 2 CTAs/SM.
// =====================================================================
__global__ void __launch_bounds__(256, 2) rnn_steps_kernel(
        const float* __restrict__ Whh, float* __restrict__ out) {
    extern __shared__ float smemf[];
    float4* hs4 = (float4*)smemf;            // [8 rows][128 f4] = 16 KB
    float*  pb  = smemf + 1024 * 4;          // [16 pid][8 rows][32 cols] = 16 KB

    const int tid = threadIdx.x;
    const int warp = tid >> 5, lane = tid & 31;
    const int c2 = lane & 15;
    const int kh = lane >> 4;

    const int mg = blockIdx.x >> 4;
    const int ng = blockIdx.x & 15;
    const int row0 = mg * 8;
    const int col0 = ng * 32;

    const int col = col0 + 2 * c2;
    const int k0 = warp * 64 + kh * 32;

    // ---- one-time W load
    unsigned long long w2[16][2];
#pragma unroll
    for (int kk = 0; kk < 16; kk++) {
        const float* p0 = Whh + (size_t)(k0 + 2 * kk) * HH + col;
        const float* p1 = p0 + HH;
        w2[kk][0] = pack2(p0[0], p1[0]);
        w2[kk][1] = pack2(p0[1], p1[1]);
    }

    const int orow = row0 + warp;
    const int ocol = col0 + lane;

    unsigned* myflag = &g_flag[(mg * 16 + ng) * 32];
    unsigned* f0 = &g_flag[(mg * 16 + 2 * warp) * 32];
    unsigned* f1 = &g_flag[(mg * 16 + 2 * warp + 1) * 32];

    const int lr = lane >> 4;
    const int lj = lane & 15;

    // ---- startup phase stagger: ~20 cyc per blockIdx unit.
    // Co-resident pair (bid, bid+148) gets a ~3000-cyc persistent offset
    // so one CTA computes while the other sits in its sync window.
    {
        float z = (float)tid;
        int iters = blockIdx.x * 5;
        for (int i = 0; i < iters; i++)
            asm volatile("add.f32 %0, %0, 1.0;" : "+f"(z));   // dep chain, 4 cyc/iter
    }

    // ---------------- t = 0 (h = 0) ----------------
    {
        float xv = __ldcg(&g_xp[(size_t)orow * HH + ocol]);
        float hv = tanhf(xv);
        g_h[1][(size_t)orow * HH + ocol] = hv;
        __syncthreads();
        if (tid == 0) { fence_rel_gpu(); st_relaxed(myflag, 1u); }
    }

    float xv = __ldcg(&g_xp[((size_t)1 * BB + orow) * HH + ocol]);

    // ---------------- t = 1 .. TT-1 ----------------
    for (int t = 1; t < TT; t++) {
        // xp[t+1] prefetch FIRST — independent of flags
        float xv_next = 0.0f;
        if (t + 1 < TT)
            xv_next = __ldcg(&g_xp[((size_t)(t + 1) * BB + orow) * HH + ocol]);

        // wait for this warp's two producers (fused condition)
        while (ld_acquire(f0) < (unsigned)t || ld_acquire(f1) < (unsigned)t) { }

        // load warp's k-chunk: 8 rows x 16 f4
        const float4* hsrc = (const float4*)g_h[t & 1];
#pragma unroll
        for (int i = 0; i < 4; i++) {
            int r = lr + 2 * i;
            hs4[r * 128 + warp * 16 + lj] =
                __ldcg(hsrc + (size_t)(row0 + r) * 128 + warp * 16 + lj);
        }
        __syncwarp();

        // ---- compute: acc[r][c] over this thread's 32 k
        unsigned long long acc[8][2];
#pragma unroll
        for (int r = 0; r < 8; r++) { acc[r][0] = 0ull; acc[r][1] = 0ull; }

        const ulonglong2* hsU = (const ulonglong2*)hs4;
#pragma unroll
        for (int r = 0; r < 8; r++) {
            const ulonglong2* hp = hsU + r * 128 + warp * 16 + kh * 8;
#pragma unroll
            for (int j = 0; j < 8; j++) {
                ulonglong2 hv2 = hp[j];
                acc[r][0] = ffma2(hv2.x, w2[2 * j][0], acc[r][0]);
                acc[r][1] = ffma2(hv2.x, w2[2 * j][1], acc[r][1]);
                acc[r][0] = ffma2(hv2.y, w2[2 * j + 1][0], acc[r][0]);
                acc[r][1] = ffma2(hv2.y, w2[2 * j + 1][1], acc[r][1]);
            }
        }

        // ---- fold k-pairs, store partials
        const int pid = warp * 2 + kh;
        float2* pb2 = (float2*)pb;
#pragma unroll
        for (int r = 0; r < 8; r++) {
            float a, b, c, d;
            unpack2(acc[r][0], a, b);
            unpack2(acc[r][1], c, d);
            pb2[(pid * 8 + r) * 16 + c2] = make_float2(a + b, c + d);
        }
        __syncthreads();

        // ---- owner reduce over 16 partials
        float s = 0.0f;
#pragma unroll
        for (int p = 0; p < 16; p++) s += pb[(p * 8 + warp) * 32 + lane];

        float hv = tanhf(xv + s);
        g_h[(t + 1) & 1][(size_t)orow * HH + ocol] = hv;
        if (t == TT - 1) out[(size_t)orow * HH + ocol] = hv;

        __syncthreads();
        if (t + 1 < TT && tid == 0) {
            fence_rel_gpu();
            st_relaxed(myflag, (unsigned)(t + 1));
        }
        xv = xv_next;
    }

    // barrier FIRST (all polls in the group done), THEN reset for replay
    group_barrier(tid, &g_ctr[mg * 32], &g_gen[mg * 32]);
    if (tid == 0) st_relaxed(myflag, 0u);
}

// =====================================================================
extern "C" void kernel_launch(void* const* d_in, const int* in_sizes, int n_in,
                              void* d_out, int out_size) {
    const float* x    = (const float*)d_in[0];
    const float* Wih  = (const float*)d_in[1];
    const float* Whh  = (const float*)d_in[2];
    const float* bias = (const float*)d_in[3];
    float* out = (float*)d_out;

    const int smem2 = 1024 * 16 + 4096 * 4;   // 32 KB
    cudaFuncSetAttribute(rnn_steps_kernel,
                         cudaFuncAttributeMaxDynamicSharedMemorySize, smem2);

    dim3 g1(HH / 128, (BB * TT) / 128);   // (4, 1024)
    xp_gemm_kernel<<<g1, 256>>>(x, Wih, bias);
    rnn_steps_kernel<<<256, 256, smem2>>>(Whh, out);
}

// round 17
// speedup vs baseline: 1.0588x; 1.0588x over previous
#include <cuda_runtime.h>
#include <math.h>

#define BB 128
#define TT 1024
#define DD 512
#define HH 512

// ---------------- scratch ----------------
__device__ float g_xp[(size_t)TT * BB * HH];   // [t][b][h]
__device__ float g_h[2][BB * HH];              // ping-pong hidden state
__device__ unsigned g_flag[16 * 16 * 32];      // flag[mg][ng] at 128B stride
__device__ unsigned g_ctr[16 * 32];
__device__ unsigned g_gen[16 * 32];

__device__ __forceinline__ unsigned long long ffma2(unsigned long long a,
                                                    unsigned long long b,
                                                    unsigned long long c) {
    unsigned long long d;
    asm("fma.rn.f32x2 %0, %1, %2, %3;" : "=l"(d) : "l"(a), "l"(b), "l"(c));
    return d;
}
__device__ __forceinline__ unsigned long long pack2(float x, float y) {
    unsigned long long d;
    asm("mov.b64 %0, {%1, %2};" : "=l"(d) : "f"(x), "f"(y));
    return d;
}
__device__ __forceinline__ void unpack2(unsigned long long v, float& x, float& y) {
    asm("mov.b64 {%0, %1}, %2;" : "=f"(x), "=f"(y) : "l"(v));
}

__device__ __forceinline__ unsigned atom_add_acqrel(unsigned* p, unsigned v) {
    unsigned old;
    asm volatile("atom.acq_rel.gpu.global.add.u32 %0, [%1], %2;"
                 : "=r"(old) : "l"(p), "r"(v) : "memory");
    return old;
}
__device__ __forceinline__ unsigned ld_acquire(unsigned* p) {
    unsigned v;
    asm volatile("ld.acquire.gpu.global.u32 %0, [%1];"
                 : "=r"(v) : "l"(p) : "memory");
    return v;
}
__device__ __forceinline__ void st_relaxed(unsigned* p, unsigned v) {
    asm volatile("st.relaxed.gpu.global.u32 [%0], %1;"
                 :: "l"(p), "r"(v) : "memory");
}
__device__ __forceinline__ void st_release(unsigned* p, unsigned v) {
    asm volatile("st.release.gpu.global.u32 [%0], %1;"
                 :: "l"(p), "r"(v) : "memory");
}

__device__ __forceinline__ void group_barrier(int tid, unsigned* ctr, unsigned* gen) {
    __syncthreads();
    if (tid == 0) {
        unsigned g = ld_acquire(gen);
        unsigned tk = atom_add_acqrel(ctr, 1u);
        if (tk == 15u) {
            st_relaxed(ctr, 0u);
            atom_add_acqrel(gen, 1u);
        } else {
            while (ld_acquire(gen) == g) { }
        }
    }
    __syncthreads();
}

// =====================================================================
// Phase 1: xp = x @ W_ih + b   (R15 version — single buffer, 2 CTAs/SM)
// =====================================================================
__global__ void __launch_bounds__(256) xp_gemm_kernel(
        const float* __restrict__ x, const float* __restrict__ Wih,
        const float* __restrict__ bias) {
    __shared__ float As[16][128];
    __shared__ float Bs[16][128];

    const int tid = threadIdx.x;
    const int tx = tid & 15;
    const int ty = tid >> 4;
    const int m0 = blockIdx.y * 128;
    const int n0 = blockIdx.x * 128;

    unsigned long long acc[8][4];
#pragma unroll
    for (int i = 0; i < 8; i++)
#pragma unroll
        for (int j = 0; j < 4; j++) acc[i][j] = 0ull;

    for (int k0 = 0; k0 < DD; k0 += 16) {
#pragma unroll
        for (int q = 0; q < 2; q++) {
            int i = tid + q * 256;
            int row = i >> 2;
            int kc = (i & 3) * 4;
            float4 av = *(const float4*)&x[(size_t)(m0 + row) * DD + k0 + kc];
            As[kc + 0][row] = av.x;
            As[kc + 1][row] = av.y;
            As[kc + 2][row] = av.z;
            As[kc + 3][row] = av.w;
        }
#pragma unroll
        for (int q = 0; q < 2; q++) {
            int i = tid + q * 256;
            int kr = i >> 5;
            int nc = (i & 31) * 4;
            float4 bv = *(const float4*)&Wih[(size_t)(k0 + kr) * HH + n0 + nc];
            *(float4*)&Bs[kr][nc] = bv;
        }
        __syncthreads();

#pragma unroll
        for (int kk = 0; kk < 16; kk++) {
            float4 a0 = *(const float4*)&As[kk][ty * 8];
            float4 a1 = *(const float4*)&As[kk][ty * 8 + 4];
            const unsigned long long* bp =
                (const unsigned long long*)&Bs[kk][tx * 8];
            unsigned long long b0 = bp[0], b1 = bp[1], b2 = bp[2], b3 = bp[3];
            float a[8] = {a0.x, a0.y, a0.z, a0.w, a1.x, a1.y, a1.z, a1.w};
#pragma unroll
            for (int i = 0; i < 8; i++) {
                unsigned long long ap = pack2(a[i], a[i]);
                acc[i][0] = ffma2(ap, b0, acc[i][0]);
                acc[i][1] = ffma2(ap, b1, acc[i][1]);
                acc[i][2] = ffma2(ap, b2, acc[i][2]);
                acc[i][3] = ffma2(ap, b3, acc[i][3]);
            }
        }
        __syncthreads();
    }

    float4 bv0 = *(const float4*)&bias[n0 + tx * 8];
    float4 bv1 = *(const float4*)&bias[n0 + tx * 8 + 4];
    float bb8[8] = {bv0.x, bv0.y, bv0.z, bv0.w, bv1.x, bv1.y, bv1.z, bv1.w};
#pragma unroll
    for (int i = 0; i < 8; i++) {
        int mrow = m0 + ty * 8 + i;
        int b_ = mrow >> 10;
        int t_ = mrow & 1023;
        float f[8];
        unpack2(acc[i][0], f[0], f[1]);
        unpack2(acc[i][1], f[2], f[3]);
        unpack2(acc[i][2], f[4], f[5]);
        unpack2(acc[i][3], f[6], f[7]);
#pragma unroll
        for (int j = 0; j < 8; j++) f[j] += bb8[j];
        float* dst = &g_xp[((size_t)t_ * BB + b_) * HH + n0 + tx * 8];
        *(float4*)&dst[0] = make_float4(f[0], f[1], f[2], f[3]);
        *(float4*)&dst[4] = make_float4(f[4], f[5], f[6], f[7]);
    }
}

// =====================================================================
// Phase 2 v9b: R15 structure (256 CTAs x 256 thr, 8 rows x 32 cols,
// 2 CTAs/SM, per-warp producer flags) + parallel dual poll + st.release.
// NO stagger (R16 showed phase-aligned L2 reuse matters).
// =====================================================================
__global__ void __launch_bounds__(256, 2) rnn_steps_kernel(
        const float* __restrict__ Whh, float* __restrict__ out) {
    extern __shared__ float smemf[];
    float4* hs4 = (float4*)smemf;            // [8 rows][128 f4] = 16 KB
    float*  pb  = smemf + 1024 * 4;          // [16 pid][8 rows][32 cols] = 16 KB

    const int tid = threadIdx.x;
    const int warp = tid >> 5, lane = tid & 31;
    const int c2 = lane & 15;
    const int kh = lane >> 4;

    const int mg = blockIdx.x >> 4;
    const int ng = blockIdx.x & 15;
    const int row0 = mg * 8;
    const int col0 = ng * 32;

    const int col = col0 + 2 * c2;
    const int k0 = warp * 64 + kh * 32;

    unsigned long long w2[16][2];
#pragma unroll
    for (int kk = 0; kk < 16; kk++) {
        const float* p0 = Whh + (size_t)(k0 + 2 * kk) * HH + col;
        const float* p1 = p0 + HH;
        w2[kk][0] = pack2(p0[0], p1[0]);
        w2[kk][1] = pack2(p0[1], p1[1]);
    }

    const int orow = row0 + warp;
    const int ocol = col0 + lane;

    unsigned* myflag = &g_flag[(mg * 16 + ng) * 32];
    unsigned* f0 = &g_flag[(mg * 16 + 2 * warp) * 32];
    unsigned* f1 = &g_flag[(mg * 16 + 2 * warp + 1) * 32];

    const int lr = lane >> 4;
    const int lj = lane & 15;

    // ---------------- t = 0 (h = 0) ----------------
    {
        float xv = __ldcg(&g_xp[(size_t)orow * HH + ocol]);
        float hv = tanhf(xv);
        g_h[1][(size_t)orow * HH + ocol] = hv;
        __syncthreads();
        if (tid == 0) st_release(myflag, 1u);
    }

    float xv = __ldcg(&g_xp[((size_t)1 * BB + orow) * HH + ocol]);

    // ---------------- t = 1 .. TT-1 ----------------
    for (int t = 1; t < TT; t++) {
        // wait for this warp's two producers — both loads in flight per iter
        for (;;) {
            unsigned a = ld_acquire(f0);
            unsigned b = ld_acquire(f1);
            if (a >= (unsigned)t && b >= (unsigned)t) break;
        }

        // load warp's k-chunk: 8 rows x 16 f4
        const float4* hsrc = (const float4*)g_h[t & 1];
#pragma unroll
        for (int i = 0; i < 4; i++) {
            int r = lr + 2 * i;
            hs4[r * 128 + warp * 16 + lj] =
                __ldcg(hsrc + (size_t)(row0 + r) * 128 + warp * 16 + lj);
        }
        float xv_next = 0.0f;
        if (t + 1 < TT)
            xv_next = __ldcg(&g_xp[((size_t)(t + 1) * BB + orow) * HH + ocol]);
        __syncwarp();

        // compute: acc[r][c] over this thread's 32 k
        unsigned long long acc[8][2];
#pragma unroll
        for (int r = 0; r < 8; r++) { acc[r][0] = 0ull; acc[r][1] = 0ull; }

        const ulonglong2* hsU = (const ulonglong2*)hs4;
#pragma unroll
        for (int r = 0; r < 8; r++) {
            const ulonglong2* hp = hsU + r * 128 + warp * 16 + kh * 8;
#pragma unroll
            for (int j = 0; j < 8; j++) {
                ulonglong2 hv2 = hp[j];
                acc[r][0] = ffma2(hv2.x, w2[2 * j][0], acc[r][0]);
                acc[r][1] = ffma2(hv2.x, w2[2 * j][1], acc[r][1]);
                acc[r][0] = ffma2(hv2.y, w2[2 * j + 1][0], acc[r][0]);
                acc[r][1] = ffma2(hv2.y, w2[2 * j + 1][1], acc[r][1]);
            }
        }

        // fold k-pairs, store partials pb[pid][r][cols 2c2, 2c2+1]
        const int pid = warp * 2 + kh;
        float2* pb2 = (float2*)pb;
#pragma unroll
        for (int r = 0; r < 8; r++) {
            float a, b, c, d;
            unpack2(acc[r][0], a, b);
            unpack2(acc[r][1], c, d);
            pb2[(pid * 8 + r) * 16 + c2] = make_float2(a + b, c + d);
        }
        __syncthreads();

        // owner (row = warp, col = lane) reduces 16 partials
        float s = 0.0f;
#pragma unroll
        for (int p = 0; p < 16; p++) s += pb[(p * 8 + warp) * 32 + lane];

        float hv = tanhf(xv + s);
        g_h[(t + 1) & 1][(size_t)orow * HH + ocol] = hv;
        if (t == TT - 1) out[(size_t)orow * HH + ocol] = hv;

        __syncthreads();
        if (t + 1 < TT && tid == 0) st_release(myflag, (unsigned)(t + 1));
        xv = xv_next;
    }

    // barrier FIRST (all polls in the group done), THEN reset for replay
    group_barrier(tid, &g_ctr[mg * 32], &g_gen[mg * 32]);
    if (tid == 0) st_relaxed(myflag, 0u);
}

// =====================================================================
extern "C" void kernel_launch(void* const* d_in, const int* in_sizes, int n_in,
                              void* d_out, int out_size) {
    const float* x    = (const float*)d_in[0];
    const float* Wih  = (const float*)d_in[1];
    const float* Whh  = (const float*)d_in[2];
    const float* bias = (const float*)d_in[3];
    float* out = (float*)d_out;

    const int smem2 = 1024 * 16 + 4096 * 4;   // 32 KB
    cudaFuncSetAttribute(rnn_steps_kernel,
                         cudaFuncAttributeMaxDynamicSharedMemorySize, smem2);

    dim3 g1(HH / 128, (BB * TT) / 128);   // (4, 1024)
    xp_gemm_kernel<<<g1, 256>>>(x, Wih, bias);
    rnn_steps_kernel<<<256, 256, smem2>>>(Whh, out);
}